// round 2
// baseline (speedup 1.0000x reference)
#include <cuda_runtime.h>
#include <math.h>

#define N_SAMP 32
#define C_TOT 256
#define CPG 16
#define GROUPS 16          // C_TOT / CPG
#define NG 512             // N_SAMP * GROUPS
#define HW 4096            // 64*64
#define NHW (N_SAMP * HW)
#define TRI 136            // 16*17/2
#define EPS 1e-5f
#define T_ITERS 5

#define K1_SPLIT 4         // blocks per (n,g) for stats
#define K1_POS (HW / K1_SPLIT)   // 1024 positions per stats block
#define K3_SPLIT 4         // blocks per (n,g) for apply
#define K3_POS (HW / K3_SPLIT)   // 1024 positions per apply block

// -------- scratch (device globals; no allocation allowed) --------
__device__ float g_sum[NG][CPG];        // per-(n,g) channel sums
__device__ float g_covt[NG][TRI];       // per-(n,g) symmetric sum of outer products
__device__ float g_A[NG][CPG * CPG];    // folded transform  weight * wm
__device__ float g_b0[NG][CPG];         // folded offset     bias - A*mean

// ------------------------------------------------------------------
// Kernel 0: zero the accumulators (graph replays must be deterministic)
// ------------------------------------------------------------------
__global__ void zero_kernel() {
    int i = blockIdx.x * blockDim.x + threadIdx.x;
    const int n_sum = NG * CPG;
    const int n_cov = NG * TRI;
    if (i < n_sum) ((float*)g_sum)[i] = 0.f;
    else if (i < n_sum + n_cov) ((float*)g_covt)[i - n_sum] = 0.f;
}

// ------------------------------------------------------------------
// Kernel 1: per-(n,g) stats — sum_c and symmetric sum of x_c * x_d
// grid = NG * K1_SPLIT blocks, 256 threads
// ------------------------------------------------------------------
__global__ __launch_bounds__(256) void stats_kernel(const float* __restrict__ x) {
    int b = blockIdx.x;
    int ng = b >> 2;                 // / K1_SPLIT
    int chunk = b & (K1_SPLIT - 1);
    int n = ng >> 4;
    int g = ng & 15;

    const float* __restrict__ xb =
        x + (size_t)(n * C_TOT + g * CPG) * HW + (size_t)chunk * K1_POS;

    float s[CPG];
    float acc[TRI];
#pragma unroll
    for (int i = 0; i < CPG; i++) s[i] = 0.f;
#pragma unroll
    for (int i = 0; i < TRI; i++) acc[i] = 0.f;

    for (int it = 0; it < K1_POS; it += 256) {
        int p = it + threadIdx.x;
        float v[CPG];
#pragma unroll
        for (int c = 0; c < CPG; c++) v[c] = xb[(size_t)c * HW + p];
#pragma unroll
        for (int i = 0; i < CPG; i++) {
            s[i] += v[i];
#pragma unroll
            for (int j = 0; j <= i; j++)
                acc[i * (i + 1) / 2 + j] += v[i] * v[j];
        }
    }

    // warp shfl reduction of all 152 values
#pragma unroll
    for (int k = 0; k < CPG; k++) {
        float v = s[k];
        v += __shfl_xor_sync(0xffffffffu, v, 16);
        v += __shfl_xor_sync(0xffffffffu, v, 8);
        v += __shfl_xor_sync(0xffffffffu, v, 4);
        v += __shfl_xor_sync(0xffffffffu, v, 2);
        v += __shfl_xor_sync(0xffffffffu, v, 1);
        s[k] = v;
    }
#pragma unroll
    for (int k = 0; k < TRI; k++) {
        float v = acc[k];
        v += __shfl_xor_sync(0xffffffffu, v, 16);
        v += __shfl_xor_sync(0xffffffffu, v, 8);
        v += __shfl_xor_sync(0xffffffffu, v, 4);
        v += __shfl_xor_sync(0xffffffffu, v, 2);
        v += __shfl_xor_sync(0xffffffffu, v, 1);
        acc[k] = v;
    }

    __shared__ float red[8][CPG + TRI];   // 8 warps x 152
    int warp = threadIdx.x >> 5;
    int lane = threadIdx.x & 31;
    if (lane == 0) {
#pragma unroll
        for (int k = 0; k < CPG; k++) red[warp][k] = s[k];
#pragma unroll
        for (int k = 0; k < TRI; k++) red[warp][CPG + k] = acc[k];
    }
    __syncthreads();

    if (threadIdx.x < CPG + TRI) {
        float t = 0.f;
#pragma unroll
        for (int w = 0; w < 8; w++) t += red[w][threadIdx.x];
        if (threadIdx.x < CPG)
            atomicAdd(&g_sum[ng][threadIdx.x], t);
        else
            atomicAdd(&g_covt[ng][threadIdx.x - CPG], t);
    }
}

// ------------------------------------------------------------------
// Kernel 2: mix stats, Newton-Schulz whitening, fold affine.
// grid = NG blocks, 256 threads; thread (i,j) owns element (i,j).
// ------------------------------------------------------------------
__global__ __launch_bounds__(256) void whiten_kernel(
    const float* __restrict__ sw_mean_w,
    const float* __restrict__ sw_var_w,
    const float* __restrict__ weight,
    const float* __restrict__ bias) {

    int ng = blockIdx.x;
    int g = ng & 15;
    int tid = threadIdx.x;
    int i = tid >> 4;
    int j = tid & 15;

    __shared__ float cov[CPG][CPG + 1];   // holds covN after scaling
    __shared__ float P[CPG][CPG + 1];
    __shared__ float T1[CPG][CPG + 1];
    __shared__ float T2[CPG][CPG + 1];
    __shared__ float meanmix[CPG];

    // symmetric triangular index for (i,j)
    int a = i > j ? i : j;
    int bb = i > j ? j : i;
    int t = a * (a + 1) / 2 + bb;

    // IW sums for this (n,g)
    float sin_ij = g_covt[ng][t];
    float msum_i = g_sum[ng][i];
    float msum_j = g_sum[ng][j];

    // BW sums: accumulate over all samples for this group
    float sbn = 0.f, mbn_i = 0.f, mbn_j = 0.f;
    for (int n2 = 0; n2 < N_SAMP; n2++) {
        int ng2 = n2 * GROUPS + g;
        sbn += g_covt[ng2][t];
        mbn_i += g_sum[ng2][i];
        mbn_j += g_sum[ng2][j];
    }

    float mi_i = msum_i * (1.0f / HW);
    float mi_j = msum_j * (1.0f / HW);
    float mb_i = mbn_i * (1.0f / NHW);
    float mb_j = mbn_j * (1.0f / NHW);

    float cov_in = sin_ij * (1.0f / HW) - mi_i * mi_j;
    float cov_bn = sbn * (1.0f / NHW) - mb_i * mb_j;

    // softmax over 2 weights (computed redundantly by every thread; cheap)
    float w0 = sw_mean_w[0], w1 = sw_mean_w[1];
    float mm = fmaxf(w0, w1);
    float e0 = expf(w0 - mm), e1 = expf(w1 - mm);
    float mw0 = e0 / (e0 + e1);
    float mw1 = 1.0f - mw0;

    float v0 = sw_var_w[0], v1 = sw_var_w[1];
    float vm = fmaxf(v0, v1);
    float f0 = expf(v0 - vm), f1 = expf(v1 - vm);
    float vw0 = f0 / (f0 + f1);
    float vw1 = 1.0f - vw0;

    float cval = vw0 * cov_bn + vw1 * cov_in + (i == j ? EPS : 0.0f);
    cov[i][j] = cval;
    if (i == 0) meanmix[j] = mw0 * mb_j + mw1 * mi_j;
    __syncthreads();

    // trace (broadcast reads from shared)
    float tr = 0.f;
#pragma unroll
    for (int k = 0; k < CPG; k++) tr += cov[k][k];
    float rTr = 1.0f / tr;

    // RACE FIX: all threads must finish reading cov[k][k] for the trace
    // before anyone overwrites cov with the scaled covN.
    __syncthreads();

    cov[i][j] = cval * rTr;          // covN
    P[i][j] = (i == j) ? 1.0f : 0.0f;
    __syncthreads();

    for (int iter = 0; iter < T_ITERS; iter++) {
        float acc = 0.f;
#pragma unroll
        for (int k = 0; k < CPG; k++) acc += P[i][k] * P[k][j];
        T1[i][j] = acc;
        __syncthreads();

        acc = 0.f;
#pragma unroll
        for (int k = 0; k < CPG; k++) acc += T1[i][k] * P[k][j];
        T2[i][j] = acc;
        __syncthreads();

        acc = 0.f;
#pragma unroll
        for (int k = 0; k < CPG; k++) acc += T2[i][k] * cov[k][j];
        float pnew = 1.5f * P[i][j] - 0.5f * acc;
        __syncthreads();
        P[i][j] = pnew;
        __syncthreads();
    }

    float wm_ij = P[i][j] * sqrtf(rTr);
    T1[i][j] = wm_ij;                // keep wm in shared for b0
    float A_ij = weight[g * CPG + i] * wm_ij;
    g_A[ng][i * CPG + j] = A_ij;
    __syncthreads();

    if (tid < CPG) {
        int c = tid;
        float wc = weight[g * CPG + c];
        float acc = 0.f;
#pragma unroll
        for (int d = 0; d < CPG; d++) acc += T1[c][d] * meanmix[d];
        g_b0[ng][c] = bias[g * CPG + c] - wc * acc;
    }
}

// ------------------------------------------------------------------
// Kernel 3: apply  out[c] = sum_d A[c][d]*x[d] + b0[c]   (float4)
// grid = NG * K3_SPLIT blocks, 256 threads, 4 positions/thread
// ------------------------------------------------------------------
__global__ __launch_bounds__(256) void apply_kernel(const float* __restrict__ x,
                                                    float* __restrict__ out) {
    int b = blockIdx.x;
    int ng = b >> 2;                 // / K3_SPLIT
    int chunk = b & (K3_SPLIT - 1);
    int n = ng >> 4;
    int g = ng & 15;
    int tid = threadIdx.x;

    __shared__ float sA[CPG][CPG];
    __shared__ float sb[CPG];
    if (tid < 256) sA[tid >> 4][tid & 15] = g_A[ng][tid];
    if (tid < CPG) sb[tid] = g_b0[ng][tid];
    __syncthreads();

    size_t base = (size_t)(n * C_TOT + g * CPG) * HW
                + (size_t)chunk * K3_POS + (size_t)tid * 4;

    float4 v[CPG];
#pragma unroll
    for (int d = 0; d < CPG; d++)
        v[d] = *(const float4*)(x + base + (size_t)d * HW);

#pragma unroll
    for (int c = 0; c < CPG; c++) {
        float bc = sb[c];
        float4 acc = make_float4(bc, bc, bc, bc);
#pragma unroll
        for (int d = 0; d < CPG; d++) {
            float a = sA[c][d];
            acc.x += a * v[d].x;
            acc.y += a * v[d].y;
            acc.z += a * v[d].z;
            acc.w += a * v[d].w;
        }
        *(float4*)(out + base + (size_t)c * HW) = acc;
    }
}

// ------------------------------------------------------------------
extern "C" void kernel_launch(void* const* d_in, const int* in_sizes, int n_in,
                              void* d_out, int out_size) {
    const float* x      = (const float*)d_in[0];
    const float* sw_m   = (const float*)d_in[1];
    const float* sw_v   = (const float*)d_in[2];
    const float* weight = (const float*)d_in[3];
    const float* bias   = (const float*)d_in[4];
    float* out = (float*)d_out;

    int zero_total = NG * CPG + NG * TRI;
    zero_kernel<<<(zero_total + 255) / 256, 256>>>();
    stats_kernel<<<NG * K1_SPLIT, 256>>>(x);
    whiten_kernel<<<NG, 256>>>(sw_m, sw_v, weight, bias);
    apply_kernel<<<NG * K3_SPLIT, 256>>>(x, out);
}